// round 7
// baseline (speedup 1.0000x reference)
#include <cuda_runtime.h>
#include <cstdint>

// Problem constants (fixed shapes per reference)
#define Bn 16
#define Sn 4096
#define Dn 128
#define Ln 8               // timesteps per warp-chunk
#define WPC 8              // warps per CTA
#define TC (Ln * WPC)      // 64 timesteps per CTA
#define NCB (Sn / TC)      // 64 CTAs per batch (lookback chain length)
#define NCTA (Bn * NCB)    // 1024 CTAs

// -------- lookback records (device globals; no allocation allowed) ---------
__device__ float g_recP[NCTA * Dn];   // CTA aggregate: vector P
__device__ float g_recQ[NCTA * Dn];   // CTA aggregate: vector Q
__device__ float g_recV[NCTA * Dn];   // CTA inclusive prefix: bst vector
__device__ float g_recM[NCTA];        // CTA aggregate scalar M
__device__ float g_recS[NCTA];        // CTA aggregate scalar S
__device__ float g_recA[NCTA];        // CTA inclusive prefix: scalar a
__device__ int   g_flag[NCTA];        // 0=none, 1=aggregate, 2=prefix

__device__ __forceinline__ float fsig(float x) {
    return __fdividef(1.0f, 1.0f + __expf(-x));
}

__device__ __forceinline__ void warp_allreduce2(float& x, float& y) {
#pragma unroll
    for (int off = 16; off; off >>= 1) {
        x += __shfl_xor_sync(0xffffffffu, x, off);
        y += __shfl_xor_sync(0xffffffffu, y, off);
    }
}

__device__ __forceinline__ int ld_acquire(const int* p) {
    int v;
    asm volatile("ld.global.acquire.gpu.b32 %0, [%1];" : "=r"(v) : "l"(p));
    return v;
}
__device__ __forceinline__ void st_release(int* p, int v) {
    asm volatile("st.global.release.gpu.b32 [%0], %1;" :: "l"(p), "r"(v) : "memory");
}
__device__ __forceinline__ void stg_stream(float4* p, float4 v) {
    asm volatile("st.global.cs.v4.f32 [%0], {%1,%2,%3,%4};"
                 :: "l"(p), "f"(v.x), "f"(v.y), "f"(v.z), "f"(v.w) : "memory");
}

// ============================================================================
// flag clear — runs first in every kernel_launch (graph-replay safe)
// ============================================================================
__global__ void clear_kernel() {
    g_flag[threadIdx.x] = 0;
}

// ============================================================================
// Fused single-pass scan kernel with decoupled lookback.
// ============================================================================
__global__ void __launch_bounds__(256, 3)
fused_kernel(const float* __restrict__ C, const float* __restrict__ V,
             const float* __restrict__ W, const float* __restrict__ enc,
             const float* __restrict__ tmod, const float* __restrict__ cmod,
             const float* __restrict__ lnw, const float* __restrict__ lnb,
             float* __restrict__ out) {
    extern __shared__ float sm[];
    float* sDD  = sm;                      // [WPC][Ln][Dn]
    float* sEV  = sDD + WPC * Ln * Dn;     // [WPC][Ln][Dn]
    float* sP   = sEV + WPC * Ln * Dn;     // [WPC][Dn]
    float* sQ   = sP + WPC * Dn;           // [WPC][Dn]
    float* sPre = sQ + WPC * Dn;           // [Dn]
    float* sM   = sPre + Dn;               // [WPC]
    float* sS   = sM + WPC;                // [WPC]
    float* sPA  = sS + WPC;                // [1]

    const int c    = blockIdx.x;
    const int b    = c >> 6;               // / NCB
    const int kc   = c & (NCB - 1);
    const int w    = threadIdx.x >> 5;
    const int lane = threadIdx.x & 31;
    const int d4   = lane * 4;
    const int t0   = kc * TC + w * Ln;

    const float4 tm = *reinterpret_cast<const float4*>(tmod + d4);
    const float4 cm = *reinterpret_cast<const float4*>(cmod + d4);
    const float4 eb = *reinterpret_cast<const float4*>(enc + b * Dn + d4);
    const float ctx0 = fsig(eb.x * cm.x) * eb.x;
    const float ctx1 = fsig(eb.y * cm.y) * eb.y;
    const float ctx2 = fsig(eb.z * cm.z) * eb.z;
    const float ctx3 = fsig(eb.w * cm.w) * eb.w;

    const size_t base = ((size_t)b * Sn + t0) * Dn + d4;
    const float4* pC = reinterpret_cast<const float4*>(C + base);
    const float4* pV = reinterpret_cast<const float4*>(V + base);
    const float4* pW = reinterpret_cast<const float4*>(W + base);
    float4* pO = reinterpret_cast<float4*>(out + base);

    // ---------------- Phase 1: local chunk aggregates --------------------
    float4 P = make_float4(1.f, 1.f, 1.f, 1.f);
    float4 Q = make_float4(0.f, 0.f, 0.f, 0.f);
    float M = 1.f, S = 0.f, mv = 0.f, sv = 0.f;

#pragma unroll
    for (int t = 0; t < Ln; ++t) {
        const float4 cc = pC[t * (Dn / 4)];
        const float4 vv = pV[t * (Dn / 4)];
        const float4 ww = pW[t * (Dn / 4)];

        const float dd0 = fsig(ww.x * tm.x), dd1 = fsig(ww.y * tm.y);
        const float dd2 = fsig(ww.z * tm.z), dd3 = fsig(ww.w * tm.w);
        const float e0 = __expf(cc.x), e1 = __expf(cc.y);
        const float e2 = __expf(cc.z), e3 = __expf(cc.w);
        const float ev0 = fmaf(e0, vv.x, ctx0);
        const float ev1 = fmaf(e1, vv.y, ctx1);
        const float ev2 = fmaf(e2, vv.z, ctx2);
        const float ev3 = fmaf(e3, vv.w, ctx3);

        float ds = (dd0 + dd1) + (dd2 + dd3);
        float es = (e0 + e1) + (e2 + e3);
        warp_allreduce2(ds, es);
        const float m = ds * (1.0f / (float)Dn);
        const float s = es;
        if (lane == t) { mv = m; sv = s; }
        S = fmaf(m, S, s);
        M *= m;

        *reinterpret_cast<float4*>(sDD + (w * Ln + t) * Dn + d4) =
            make_float4(dd0, dd1, dd2, dd3);
        *reinterpret_cast<float4*>(sEV + (w * Ln + t) * Dn + d4) =
            make_float4(ev0, ev1, ev2, ev3);

        Q.x = fmaf(dd0, Q.x, ev0);
        Q.y = fmaf(dd1, Q.y, ev1);
        Q.z = fmaf(dd2, Q.z, ev2);
        Q.w = fmaf(dd3, Q.w, ev3);
        P.x *= dd0; P.y *= dd1; P.z *= dd2; P.w *= dd3;
    }
    *reinterpret_cast<float4*>(sP + w * Dn + d4) = P;
    *reinterpret_cast<float4*>(sQ + w * Dn + d4) = Q;
    if (lane == 0) { sM[w] = M; sS[w] = S; }
    __syncthreads();

    // ---------------- Phase 2 (warp 0): CTA aggregate + lookback ---------
    if (w == 0) {
        float4 Pc = make_float4(1.f, 1.f, 1.f, 1.f);
        float4 Qc = make_float4(0.f, 0.f, 0.f, 0.f);
        float Mc = 1.f, Sc = 0.f;
#pragma unroll
        for (int ww2 = 0; ww2 < WPC; ++ww2) {
            const float4 Pw = *reinterpret_cast<const float4*>(sP + ww2 * Dn + d4);
            const float4 Qw = *reinterpret_cast<const float4*>(sQ + ww2 * Dn + d4);
            Qc.x = fmaf(Pw.x, Qc.x, Qw.x);
            Qc.y = fmaf(Pw.y, Qc.y, Qw.y);
            Qc.z = fmaf(Pw.z, Qc.z, Qw.z);
            Qc.w = fmaf(Pw.w, Qc.w, Qw.w);
            Pc.x *= Pw.x; Pc.y *= Pw.y; Pc.z *= Pw.z; Pc.w *= Pw.w;
            const float mw = sM[ww2], sw = sS[ww2];
            Sc = fmaf(mw, Sc, sw);
            Mc *= mw;
        }

        float4 pre = make_float4(0.f, 0.f, 0.f, 0.f);
        float prea = 0.f;

        if (kc == 0) {
            // prefix = aggregate applied to zero state
            *reinterpret_cast<float4*>(&g_recV[c * Dn + d4]) = Qc;
            if (lane == 0) g_recA[c] = Sc;
            __threadfence();
            __syncwarp();
            if (lane == 0) st_release(&g_flag[c], 2);
        } else {
            *reinterpret_cast<float4*>(&g_recP[c * Dn + d4]) = Pc;
            *reinterpret_cast<float4*>(&g_recQ[c * Dn + d4]) = Qc;
            if (lane == 0) { g_recM[c] = Mc; g_recS[c] = Sc; }
            __threadfence();
            __syncwarp();
            if (lane == 0) st_release(&g_flag[c], 1);

            // decoupled lookback
            float4 Pa = make_float4(1.f, 1.f, 1.f, 1.f);
            float4 Qa = make_float4(0.f, 0.f, 0.f, 0.f);
            float Ma = 1.f, Sa = 0.f;
            int j = c - 1;
            while (true) {
                int f;
                do { f = ld_acquire(&g_flag[j]); } while (f == 0);
                const bool usePref = __all_sync(0xffffffffu, f == 2);
                if (usePref) {
                    const float4 v = *reinterpret_cast<const float4*>(&g_recV[j * Dn + d4]);
                    const float av = g_recA[j];
                    pre.x = fmaf(Pa.x, v.x, Qa.x);
                    pre.y = fmaf(Pa.y, v.y, Qa.y);
                    pre.z = fmaf(Pa.z, v.z, Qa.z);
                    pre.w = fmaf(Pa.w, v.w, Qa.w);
                    prea  = fmaf(Ma, av, Sa);
                    break;
                } else {
                    const float4 Pj = *reinterpret_cast<const float4*>(&g_recP[j * Dn + d4]);
                    const float4 Qj = *reinterpret_cast<const float4*>(&g_recQ[j * Dn + d4]);
                    Qa.x = fmaf(Pa.x, Qj.x, Qa.x);
                    Qa.y = fmaf(Pa.y, Qj.y, Qa.y);
                    Qa.z = fmaf(Pa.z, Qj.z, Qa.z);
                    Qa.w = fmaf(Pa.w, Qj.w, Qa.w);
                    Pa.x *= Pj.x; Pa.y *= Pj.y; Pa.z *= Pj.z; Pa.w *= Pj.w;
                    const float Mj = g_recM[j], Sj = g_recS[j];
                    Sa = fmaf(Ma, Sj, Sa);
                    Ma *= Mj;
                    --j;
                }
            }

            // publish own inclusive prefix
            float4 vc;
            vc.x = fmaf(Pc.x, pre.x, Qc.x);
            vc.y = fmaf(Pc.y, pre.y, Qc.y);
            vc.z = fmaf(Pc.z, pre.z, Qc.z);
            vc.w = fmaf(Pc.w, pre.w, Qc.w);
            *reinterpret_cast<float4*>(&g_recV[c * Dn + d4]) = vc;
            if (lane == 0) g_recA[c] = fmaf(Mc, prea, Sc);
            __threadfence();
            __syncwarp();
            if (lane == 0) st_release(&g_flag[c], 2);
        }

        *reinterpret_cast<float4*>(sPre + d4) = pre;
        if (lane == 0) sPA[0] = prea;
    }
    __syncthreads();

    // ---------------- Phase 3: intra-CTA prefix + replay ------------------
    float4 bst = *reinterpret_cast<const float4*>(sPre + d4);
    float a = sPA[0];
    for (int ww2 = 0; ww2 < w; ++ww2) {
        const float4 Pw = *reinterpret_cast<const float4*>(sP + ww2 * Dn + d4);
        const float4 Qw = *reinterpret_cast<const float4*>(sQ + ww2 * Dn + d4);
        bst.x = fmaf(Pw.x, bst.x, Qw.x);
        bst.y = fmaf(Pw.y, bst.y, Qw.y);
        bst.z = fmaf(Pw.z, bst.z, Qw.z);
        bst.w = fmaf(Pw.w, bst.w, Qw.w);
        a = fmaf(sM[ww2], a, sS[ww2]);
    }

    const float4 lw = *reinterpret_cast<const float4*>(lnw + d4);
    const float4 lb = *reinterpret_cast<const float4*>(lnb + d4);

#pragma unroll
    for (int t = 0; t < Ln; ++t) {
        const float4 dd = *reinterpret_cast<const float4*>(sDD + (w * Ln + t) * Dn + d4);
        const float4 ev = *reinterpret_cast<const float4*>(sEV + (w * Ln + t) * Dn + d4);
        const float m_t = __shfl_sync(0xffffffffu, mv, t);
        const float s_t = __shfl_sync(0xffffffffu, sv, t);
        a = fmaf(m_t, a, s_t);

        bst.x = fmaf(dd.x, bst.x, ev.x);
        bst.y = fmaf(dd.y, bst.y, ev.y);
        bst.z = fmaf(dd.z, bst.z, ev.z);
        bst.w = fmaf(dd.w, bst.w, ev.w);

        const float rinv = __fdividef(1.0f, a + 1e-8f);
        const float o0 = bst.x * rinv, o1 = bst.y * rinv;
        const float o2 = bst.z * rinv, o3 = bst.w * rinv;

        float lsum = (o0 + o1) + (o2 + o3);
        float lsq  = fmaf(o0, o0, fmaf(o1, o1, fmaf(o2, o2, o3 * o3)));
        warp_allreduce2(lsum, lsq);
        const float mu  = lsum * (1.0f / (float)Dn);
        const float var = fmaf(-mu, mu, lsq * (1.0f / (float)Dn));
        const float rstd = rsqrtf(var + 1e-5f);

        float4 r;
        r.x = fmaf((o0 - mu) * rstd, lw.x, lb.x);
        r.y = fmaf((o1 - mu) * rstd, lw.y, lb.y);
        r.z = fmaf((o2 - mu) * rstd, lw.z, lb.z);
        r.w = fmaf((o3 - mu) * rstd, lw.w, lb.w);
        stg_stream(pO + t * (Dn / 4), r);
    }
}

// ============================================================================
static const int SMEM_BYTES =
    (2 * WPC * Ln * Dn + 2 * WPC * Dn + Dn + 2 * WPC + 8) * (int)sizeof(float);

extern "C" void kernel_launch(void* const* d_in, const int* in_sizes, int n_in,
                              void* d_out, int out_size) {
    (void)in_sizes; (void)n_in; (void)out_size;
    const float* C    = (const float*)d_in[0];
    const float* V    = (const float*)d_in[1];
    const float* W    = (const float*)d_in[2];
    const float* enc  = (const float*)d_in[3];
    const float* tmod = (const float*)d_in[4];
    const float* cmod = (const float*)d_in[5];
    const float* lnw  = (const float*)d_in[6];
    const float* lnb  = (const float*)d_in[7];
    float* out = (float*)d_out;

    cudaFuncSetAttribute(fused_kernel,
                         cudaFuncAttributeMaxDynamicSharedMemorySize, SMEM_BYTES);

    clear_kernel<<<1, NCTA>>>();
    fused_kernel<<<NCTA, 256, SMEM_BYTES>>>(C, V, W, enc, tmod, cmod, lnw, lnb, out);
}

// round 8
// speedup vs baseline: 1.0055x; 1.0055x over previous
#include <cuda_runtime.h>
#include <cstdint>

// Problem constants (fixed shapes per reference)
#define Bn 16
#define Sn 4096
#define Dn 128
#define Ln 8               // timesteps per warp-chunk
#define WPC 8              // warps per CTA
#define TC (Ln * WPC)      // 64 timesteps per CTA
#define NCB (Sn / TC)      // 64 CTAs per batch (lookback chain length)
#define NCTA (Bn * NCB)    // 1024 CTAs
#define LBW 4              // lookback window (records combined per round trip)

// -------- lookback records (device globals; no allocation allowed) ---------
__device__ float g_recP[NCTA * Dn];   // CTA aggregate: vector P
__device__ float g_recQ[NCTA * Dn];   // CTA aggregate: vector Q
__device__ float g_recV[NCTA * Dn];   // CTA inclusive prefix: bst vector
__device__ float g_recM[NCTA];        // CTA aggregate scalar M
__device__ float g_recS[NCTA];        // CTA aggregate scalar S
__device__ float g_recA[NCTA];        // CTA inclusive prefix: scalar a
__device__ int   g_flag[NCTA];        // 0=none, 1=aggregate, 2=prefix

__device__ __forceinline__ float fsig(float x) {
    return __fdividef(1.0f, 1.0f + __expf(-x));
}

__device__ __forceinline__ void warp_allreduce2(float& x, float& y) {
#pragma unroll
    for (int off = 16; off; off >>= 1) {
        x += __shfl_xor_sync(0xffffffffu, x, off);
        y += __shfl_xor_sync(0xffffffffu, y, off);
    }
}

__device__ __forceinline__ int ld_acquire(const int* p) {
    int v;
    asm volatile("ld.global.acquire.gpu.b32 %0, [%1];" : "=r"(v) : "l"(p));
    return v;
}
__device__ __forceinline__ void st_release(int* p, int v) {
    asm volatile("st.global.release.gpu.b32 [%0], %1;" :: "l"(p), "r"(v) : "memory");
}
__device__ __forceinline__ void stg_stream(float4* p, float4 v) {
    asm volatile("st.global.cs.v4.f32 [%0], {%1,%2,%3,%4};"
                 :: "l"(p), "f"(v.x), "f"(v.y), "f"(v.z), "f"(v.w) : "memory");
}

// ============================================================================
// flag clear — runs first in every kernel_launch (graph-replay safe)
// ============================================================================
__global__ void clear_kernel() {
    g_flag[threadIdx.x] = 0;
}

// ============================================================================
// Fused single-pass scan kernel with windowed decoupled lookback.
// ============================================================================
__global__ void __launch_bounds__(256, 3)
fused_kernel(const float* __restrict__ C, const float* __restrict__ V,
             const float* __restrict__ W, const float* __restrict__ enc,
             const float* __restrict__ tmod, const float* __restrict__ cmod,
             const float* __restrict__ lnw, const float* __restrict__ lnb,
             float* __restrict__ out) {
    extern __shared__ float sm[];
    float* sDD  = sm;                      // [WPC][Ln][Dn]
    float* sEV  = sDD + WPC * Ln * Dn;     // [WPC][Ln][Dn]
    float* sP   = sEV + WPC * Ln * Dn;     // [WPC][Dn]
    float* sQ   = sP + WPC * Dn;           // [WPC][Dn]
    float* sPre = sQ + WPC * Dn;           // [Dn]
    float* sM   = sPre + Dn;               // [WPC]
    float* sS   = sM + WPC;                // [WPC]
    float* sPA  = sS + WPC;                // [1]

    const int c    = blockIdx.x;
    const int b    = c >> 6;               // / NCB
    const int kc   = c & (NCB - 1);
    const int cbase = b << 6;              // first CTA of this chain
    const int w    = threadIdx.x >> 5;
    const int lane = threadIdx.x & 31;
    const int d4   = lane * 4;
    const int t0   = kc * TC + w * Ln;

    const float4 tm = *reinterpret_cast<const float4*>(tmod + d4);
    const float4 cm = *reinterpret_cast<const float4*>(cmod + d4);
    const float4 eb = *reinterpret_cast<const float4*>(enc + b * Dn + d4);
    const float ctx0 = fsig(eb.x * cm.x) * eb.x;
    const float ctx1 = fsig(eb.y * cm.y) * eb.y;
    const float ctx2 = fsig(eb.z * cm.z) * eb.z;
    const float ctx3 = fsig(eb.w * cm.w) * eb.w;

    const size_t base = ((size_t)b * Sn + t0) * Dn + d4;
    const float4* pC = reinterpret_cast<const float4*>(C + base);
    const float4* pV = reinterpret_cast<const float4*>(V + base);
    const float4* pW = reinterpret_cast<const float4*>(W + base);
    float4* pO = reinterpret_cast<float4*>(out + base);

    // ---------------- Phase 1: local chunk aggregates --------------------
    float4 P = make_float4(1.f, 1.f, 1.f, 1.f);
    float4 Q = make_float4(0.f, 0.f, 0.f, 0.f);
    float M = 1.f, S = 0.f, mv = 0.f, sv = 0.f;

#pragma unroll
    for (int t = 0; t < Ln; ++t) {
        const float4 cc = pC[t * (Dn / 4)];
        const float4 vv = pV[t * (Dn / 4)];
        const float4 ww = pW[t * (Dn / 4)];

        const float dd0 = fsig(ww.x * tm.x), dd1 = fsig(ww.y * tm.y);
        const float dd2 = fsig(ww.z * tm.z), dd3 = fsig(ww.w * tm.w);
        const float e0 = __expf(cc.x), e1 = __expf(cc.y);
        const float e2 = __expf(cc.z), e3 = __expf(cc.w);
        const float ev0 = fmaf(e0, vv.x, ctx0);
        const float ev1 = fmaf(e1, vv.y, ctx1);
        const float ev2 = fmaf(e2, vv.z, ctx2);
        const float ev3 = fmaf(e3, vv.w, ctx3);

        float ds = (dd0 + dd1) + (dd2 + dd3);
        float es = (e0 + e1) + (e2 + e3);
        warp_allreduce2(ds, es);
        const float m = ds * (1.0f / (float)Dn);
        const float s = es;
        if (lane == t) { mv = m; sv = s; }
        S = fmaf(m, S, s);
        M *= m;

        *reinterpret_cast<float4*>(sDD + (w * Ln + t) * Dn + d4) =
            make_float4(dd0, dd1, dd2, dd3);
        *reinterpret_cast<float4*>(sEV + (w * Ln + t) * Dn + d4) =
            make_float4(ev0, ev1, ev2, ev3);

        Q.x = fmaf(dd0, Q.x, ev0);
        Q.y = fmaf(dd1, Q.y, ev1);
        Q.z = fmaf(dd2, Q.z, ev2);
        Q.w = fmaf(dd3, Q.w, ev3);
        P.x *= dd0; P.y *= dd1; P.z *= dd2; P.w *= dd3;
    }
    *reinterpret_cast<float4*>(sP + w * Dn + d4) = P;
    *reinterpret_cast<float4*>(sQ + w * Dn + d4) = Q;
    if (lane == 0) { sM[w] = M; sS[w] = S; }
    __syncthreads();

    // ---------------- Phase 2 (warp 0): CTA aggregate + windowed lookback
    // Meanwhile warps 1..7 compose their intra-CTA prefix transforms.
    float4 Pcum = make_float4(1.f, 1.f, 1.f, 1.f);
    float4 Qcum = make_float4(0.f, 0.f, 0.f, 0.f);
    float Mcum = 1.f, Scum = 0.f;
    if (w != 0) {
        for (int ww2 = 0; ww2 < w; ++ww2) {
            const float4 Pw = *reinterpret_cast<const float4*>(sP + ww2 * Dn + d4);
            const float4 Qw = *reinterpret_cast<const float4*>(sQ + ww2 * Dn + d4);
            Qcum.x = fmaf(Pw.x, Qcum.x, Qw.x);
            Qcum.y = fmaf(Pw.y, Qcum.y, Qw.y);
            Qcum.z = fmaf(Pw.z, Qcum.z, Qw.z);
            Qcum.w = fmaf(Pw.w, Qcum.w, Qw.w);
            Pcum.x *= Pw.x; Pcum.y *= Pw.y; Pcum.z *= Pw.z; Pcum.w *= Pw.w;
            const float mw = sM[ww2], sw = sS[ww2];
            Scum = fmaf(mw, Scum, sw);
            Mcum *= mw;
        }
    } else {
        // CTA aggregate over all 8 warps
        float4 Pc = make_float4(1.f, 1.f, 1.f, 1.f);
        float4 Qc = make_float4(0.f, 0.f, 0.f, 0.f);
        float Mc = 1.f, Sc = 0.f;
#pragma unroll
        for (int ww2 = 0; ww2 < WPC; ++ww2) {
            const float4 Pw = *reinterpret_cast<const float4*>(sP + ww2 * Dn + d4);
            const float4 Qw = *reinterpret_cast<const float4*>(sQ + ww2 * Dn + d4);
            Qc.x = fmaf(Pw.x, Qc.x, Qw.x);
            Qc.y = fmaf(Pw.y, Qc.y, Qw.y);
            Qc.z = fmaf(Pw.z, Qc.z, Qw.z);
            Qc.w = fmaf(Pw.w, Qc.w, Qw.w);
            Pc.x *= Pw.x; Pc.y *= Pw.y; Pc.z *= Pw.z; Pc.w *= Pw.w;
            const float mw = sM[ww2], sw = sS[ww2];
            Sc = fmaf(mw, Sc, sw);
            Mc *= mw;
        }

        float4 pre = make_float4(0.f, 0.f, 0.f, 0.f);
        float prea = 0.f;

        if (kc == 0) {
            *reinterpret_cast<float4*>(&g_recV[c * Dn + d4]) = Qc;
            if (lane == 0) g_recA[c] = Sc;
            __threadfence();
            __syncwarp();
            if (lane == 0) st_release(&g_flag[c], 2);
        } else {
            *reinterpret_cast<float4*>(&g_recP[c * Dn + d4]) = Pc;
            *reinterpret_cast<float4*>(&g_recQ[c * Dn + d4]) = Qc;
            if (lane == 0) { g_recM[c] = Mc; g_recS[c] = Sc; }
            __threadfence();
            __syncwarp();
            if (lane == 0) st_release(&g_flag[c], 1);

            // windowed decoupled lookback: combine up to LBW records per trip
            float4 Pa = make_float4(1.f, 1.f, 1.f, 1.f);
            float4 Qa = make_float4(0.f, 0.f, 0.f, 0.f);
            float Ma = 1.f, Sa = 0.f;
            int j = c - 1;
            while (true) {
                int fl = 0;
                const int idx = j - lane;
                const bool valid = (lane < LBW) && (idx >= cbase);
                if (valid) fl = ld_acquire(&g_flag[idx]);
                const unsigned okm = __ballot_sync(0xffffffffu, valid && fl >= 1);
                const unsigned pfm = __ballot_sync(0xffffffffu, valid && fl == 2);
                int n = __ffs(~okm) - 1;      // consecutive-ready count from i=0
                if (n <= 0) continue;
                const int ip = __ffs(pfm & ((1u << n) - 1u));  // 1-based, 0 if none
                const bool hasPref = (ip != 0);
                if (hasPref) n = ip;

                // parallel record loads (prefix folded in as P=0, Q=recV)
                float4 rP[LBW], rQ[LBW];
                float rM[LBW], rS[LBW];
#pragma unroll
                for (int i = 0; i < LBW; ++i) {
                    if (i < n) {
                        const int jj = j - i;
                        const bool isPref = hasPref && (i == n - 1);
                        if (isPref) {
                            rP[i] = make_float4(0.f, 0.f, 0.f, 0.f);
                            rQ[i] = *reinterpret_cast<const float4*>(&g_recV[jj * Dn + d4]);
                            rM[i] = 0.f;
                            rS[i] = g_recA[jj];
                        } else {
                            rP[i] = *reinterpret_cast<const float4*>(&g_recP[jj * Dn + d4]);
                            rQ[i] = *reinterpret_cast<const float4*>(&g_recQ[jj * Dn + d4]);
                            rM[i] = g_recM[jj];
                            rS[i] = g_recS[jj];
                        }
                    }
                }
                // in-register combine (descending index order)
#pragma unroll
                for (int i = 0; i < LBW; ++i) {
                    if (i < n) {
                        Qa.x = fmaf(Pa.x, rQ[i].x, Qa.x);
                        Qa.y = fmaf(Pa.y, rQ[i].y, Qa.y);
                        Qa.z = fmaf(Pa.z, rQ[i].z, Qa.z);
                        Qa.w = fmaf(Pa.w, rQ[i].w, Qa.w);
                        Pa.x *= rP[i].x; Pa.y *= rP[i].y;
                        Pa.z *= rP[i].z; Pa.w *= rP[i].w;
                        Sa = fmaf(Ma, rS[i], Sa);
                        Ma *= rM[i];
                    }
                }
                if (hasPref) { pre = Qa; prea = Sa; break; }
                j -= n;
            }

            // publish own inclusive prefix
            float4 vc;
            vc.x = fmaf(Pc.x, pre.x, Qc.x);
            vc.y = fmaf(Pc.y, pre.y, Qc.y);
            vc.z = fmaf(Pc.z, pre.z, Qc.z);
            vc.w = fmaf(Pc.w, pre.w, Qc.w);
            *reinterpret_cast<float4*>(&g_recV[c * Dn + d4]) = vc;
            if (lane == 0) g_recA[c] = fmaf(Mc, prea, Sc);
            __threadfence();
            __syncwarp();
            if (lane == 0) st_release(&g_flag[c], 2);
        }

        *reinterpret_cast<float4*>(sPre + d4) = pre;
        if (lane == 0) sPA[0] = prea;
    }
    __syncthreads();

    // ---------------- Phase 3: apply prefix + replay ----------------------
    const float4 pre = *reinterpret_cast<const float4*>(sPre + d4);
    const float prea = sPA[0];
    float4 bst;
    bst.x = fmaf(Pcum.x, pre.x, Qcum.x);
    bst.y = fmaf(Pcum.y, pre.y, Qcum.y);
    bst.z = fmaf(Pcum.z, pre.z, Qcum.z);
    bst.w = fmaf(Pcum.w, pre.w, Qcum.w);
    float a = fmaf(Mcum, prea, Scum);

    const float4 lw = *reinterpret_cast<const float4*>(lnw + d4);
    const float4 lb = *reinterpret_cast<const float4*>(lnb + d4);

#pragma unroll
    for (int t = 0; t < Ln; ++t) {
        const float4 dd = *reinterpret_cast<const float4*>(sDD + (w * Ln + t) * Dn + d4);
        const float4 ev = *reinterpret_cast<const float4*>(sEV + (w * Ln + t) * Dn + d4);
        const float m_t = __shfl_sync(0xffffffffu, mv, t);
        const float s_t = __shfl_sync(0xffffffffu, sv, t);
        a = fmaf(m_t, a, s_t);

        bst.x = fmaf(dd.x, bst.x, ev.x);
        bst.y = fmaf(dd.y, bst.y, ev.y);
        bst.z = fmaf(dd.z, bst.z, ev.z);
        bst.w = fmaf(dd.w, bst.w, ev.w);

        const float rinv = __fdividef(1.0f, a + 1e-8f);
        const float o0 = bst.x * rinv, o1 = bst.y * rinv;
        const float o2 = bst.z * rinv, o3 = bst.w * rinv;

        float lsum = (o0 + o1) + (o2 + o3);
        float lsq  = fmaf(o0, o0, fmaf(o1, o1, fmaf(o2, o2, o3 * o3)));
        warp_allreduce2(lsum, lsq);
        const float mu  = lsum * (1.0f / (float)Dn);
        const float var = fmaf(-mu, mu, lsq * (1.0f / (float)Dn));
        const float rstd = rsqrtf(var + 1e-5f);

        float4 r;
        r.x = fmaf((o0 - mu) * rstd, lw.x, lb.x);
        r.y = fmaf((o1 - mu) * rstd, lw.y, lb.y);
        r.z = fmaf((o2 - mu) * rstd, lw.z, lb.z);
        r.w = fmaf((o3 - mu) * rstd, lw.w, lb.w);
        stg_stream(pO + t * (Dn / 4), r);
    }
}

// ============================================================================
static const int SMEM_BYTES =
    (2 * WPC * Ln * Dn + 2 * WPC * Dn + Dn + 2 * WPC + 8) * (int)sizeof(float);

extern "C" void kernel_launch(void* const* d_in, const int* in_sizes, int n_in,
                              void* d_out, int out_size) {
    (void)in_sizes; (void)n_in; (void)out_size;
    const float* C    = (const float*)d_in[0];
    const float* V    = (const float*)d_in[1];
    const float* W    = (const float*)d_in[2];
    const float* enc  = (const float*)d_in[3];
    const float* tmod = (const float*)d_in[4];
    const float* cmod = (const float*)d_in[5];
    const float* lnw  = (const float*)d_in[6];
    const float* lnb  = (const float*)d_in[7];
    float* out = (float*)d_out;

    cudaFuncSetAttribute(fused_kernel,
                         cudaFuncAttributeMaxDynamicSharedMemorySize, SMEM_BYTES);

    clear_kernel<<<1, NCTA>>>();
    fused_kernel<<<NCTA, 256, SMEM_BYTES>>>(C, V, W, enc, tmod, cmod, lnw, lnb, out);
}

// round 9
// speedup vs baseline: 1.3423x; 1.3349x over previous
#include <cuda_runtime.h>
#include <cstdint>

// Problem constants (fixed shapes per reference)
#define Bn 16
#define Sn 4096
#define Dn 128
#define Ln 8             // timesteps per chunk (data-parallel passes)
#define NCn (Sn / Ln)    // 512 chunks per batch
#define GC 16            // chunks per group (scan hierarchy)
#define NG (NCn / GC)    // 32 groups per batch
#define TG (GC * Ln)     // 128 timesteps per group
#define LPL (TG / 32)    // 4 timesteps per lane in group scalar scan

// -------- scratch (device globals; no allocation allowed) --------
__device__ float g_m   [Bn * Sn];
__device__ float g_s   [Bn * Sn];
__device__ float g_rinv[Bn * Sn];
__device__ float g_P   [Bn * NCn * Dn];
__device__ float g_Q   [Bn * NCn * Dn];
__device__ float g_b0  [Bn * NCn * Dn];
__device__ float g_GP  [Bn * NG * Dn];
__device__ float g_GQ  [Bn * NG * Dn];
__device__ float g_laneM[Bn * NG * 32];
__device__ float g_laneS[Bn * NG * 32];
__device__ float g_GAM [Bn * NG];
__device__ float g_GAS [Bn * NG];

__device__ __forceinline__ float fsig(float x) {
    return __fdividef(1.0f, 1.0f + __expf(-x));
}

// ---- reduce-scatter: v[8] per lane -> returns sum over warp of v[lane&7] --
__device__ __forceinline__ float rs8(const float* v, int lane) {
    const bool b1 = lane & 1;
    float k0 = b1 ? v[1] : v[0], o0 = b1 ? v[0] : v[1];
    float k1 = b1 ? v[3] : v[2], o1 = b1 ? v[2] : v[3];
    float k2 = b1 ? v[5] : v[4], o2 = b1 ? v[4] : v[5];
    float k3 = b1 ? v[7] : v[6], o3 = b1 ? v[6] : v[7];
    k0 += __shfl_xor_sync(0xffffffffu, o0, 1);
    k1 += __shfl_xor_sync(0xffffffffu, o1, 1);
    k2 += __shfl_xor_sync(0xffffffffu, o2, 1);
    k3 += __shfl_xor_sync(0xffffffffu, o3, 1);
    const bool b2 = lane & 2;
    float m0 = b2 ? k1 : k0, n0 = b2 ? k0 : k1;
    float m1 = b2 ? k3 : k2, n1 = b2 ? k2 : k3;
    m0 += __shfl_xor_sync(0xffffffffu, n0, 2);
    m1 += __shfl_xor_sync(0xffffffffu, n1, 2);
    const bool b4 = lane & 4;
    float p = b4 ? m1 : m0, q = b4 ? m0 : m1;
    p += __shfl_xor_sync(0xffffffffu, q, 4);
    p += __shfl_xor_sync(0xffffffffu, p, 8);
    p += __shfl_xor_sync(0xffffffffu, p, 16);
    return p;
}

// ---- reduce-scatter: 4 values -> sum over warp of v[lane&3] ---------------
__device__ __forceinline__ float rs4(float v0, float v1, float v2, float v3,
                                     int lane) {
    const bool b1 = lane & 1;
    float k0 = b1 ? v1 : v0, o0 = b1 ? v0 : v1;
    float k1 = b1 ? v3 : v2, o1 = b1 ? v2 : v3;
    k0 += __shfl_xor_sync(0xffffffffu, o0, 1);
    k1 += __shfl_xor_sync(0xffffffffu, o1, 1);
    const bool b2 = lane & 2;
    float p = b2 ? k1 : k0, q = b2 ? k0 : k1;
    p += __shfl_xor_sync(0xffffffffu, q, 2);
    p += __shfl_xor_sync(0xffffffffu, p, 4);
    p += __shfl_xor_sync(0xffffffffu, p, 8);
    p += __shfl_xor_sync(0xffffffffu, p, 16);
    return p;
}

// ---- cache-policy loads/stores ---------------------------------------------
// NOTE: loads are NON-volatile asm so the compiler may hoist/batch them (MLP).
__device__ __forceinline__ uint64_t pol_evict_last() {
    uint64_t p;
    asm("createpolicy.fractional.L2::evict_last.b64 %0, 1.0;" : "=l"(p));
    return p;
}
__device__ __forceinline__ uint64_t pol_evict_first() {
    uint64_t p;
    asm("createpolicy.fractional.L2::evict_first.b64 %0, 1.0;" : "=l"(p));
    return p;
}
__device__ __forceinline__ float4 ldg_pol(const float4* p, uint64_t pol) {
    float4 r;
    asm("ld.global.nc.L2::cache_hint.v4.f32 {%0,%1,%2,%3}, [%4], %5;"
        : "=f"(r.x), "=f"(r.y), "=f"(r.z), "=f"(r.w)
        : "l"(p), "l"(pol));
    return r;
}
__device__ __forceinline__ void stg_stream(float4* p, float4 v) {
    asm volatile("st.global.cs.v4.f32 [%0], {%1,%2,%3,%4};"
                 :: "l"(p), "f"(v.x), "f"(v.y), "f"(v.z), "f"(v.w) : "memory");
}

// ============================================================================
// Pass A: per-chunk aggregates. One warp per (batch, chunk); lane owns 4 ch.
// No shuffles inside the load loop — m/s reductions batched after it.
// ============================================================================
__global__ void __launch_bounds__(256)
passA_kernel(const float* __restrict__ C, const float* __restrict__ V,
             const float* __restrict__ W, const float* __restrict__ enc,
             const float* __restrict__ tmod, const float* __restrict__ cmod) {
    const int warp = (blockIdx.x * blockDim.x + threadIdx.x) >> 5;
    const int lane = threadIdx.x & 31;
    const int b = warp >> 9;
    const int k = warp & (NCn - 1);
    const int t0 = k * Ln;
    const int d4 = lane * 4;

    const uint64_t pol = pol_evict_last();

    const float4 tm = *reinterpret_cast<const float4*>(tmod + d4);
    const float4 cm = *reinterpret_cast<const float4*>(cmod + d4);
    const float4 eb = *reinterpret_cast<const float4*>(enc + b * Dn + d4);
    const float ctx0 = fsig(eb.x * cm.x) * eb.x;
    const float ctx1 = fsig(eb.y * cm.y) * eb.y;
    const float ctx2 = fsig(eb.z * cm.z) * eb.z;
    const float ctx3 = fsig(eb.w * cm.w) * eb.w;

    const size_t base = ((size_t)b * Sn + t0) * Dn + d4;
    const float4* pC = reinterpret_cast<const float4*>(C + base);
    const float4* pV = reinterpret_cast<const float4*>(V + base);
    const float4* pW = reinterpret_cast<const float4*>(W + base);

    float P0 = 1.f, P1 = 1.f, P2 = 1.f, P3 = 1.f;
    float Q0 = 0.f, Q1 = 0.f, Q2 = 0.f, Q3 = 0.f;
    float ds[Ln], es[Ln];

#pragma unroll
    for (int t = 0; t < Ln; ++t) {
        const float4 c = ldg_pol(pC + t * (Dn / 4), pol);
        const float4 v = ldg_pol(pV + t * (Dn / 4), pol);
        const float4 w = ldg_pol(pW + t * (Dn / 4), pol);

        const float dd0 = fsig(w.x * tm.x), dd1 = fsig(w.y * tm.y);
        const float dd2 = fsig(w.z * tm.z), dd3 = fsig(w.w * tm.w);
        const float e0 = __expf(c.x), e1 = __expf(c.y);
        const float e2 = __expf(c.z), e3 = __expf(c.w);

        ds[t] = (dd0 + dd1) + (dd2 + dd3);
        es[t] = (e0 + e1) + (e2 + e3);

        Q0 = fmaf(dd0, Q0, fmaf(e0, v.x, ctx0));
        Q1 = fmaf(dd1, Q1, fmaf(e1, v.y, ctx1));
        Q2 = fmaf(dd2, Q2, fmaf(e2, v.z, ctx2));
        Q3 = fmaf(dd3, Q3, fmaf(e3, v.w, ctx3));
        P0 *= dd0; P1 *= dd1; P2 *= dd2; P3 *= dd3;
    }

    // batched reduce-scatter: lane l gets sums for t = l&7
    const float msum = rs8(ds, lane);
    const float ssum = rs8(es, lane);
    if (lane < Ln) {
        g_m[b * Sn + t0 + lane] = msum * (1.0f / (float)Dn);
        g_s[b * Sn + t0 + lane] = ssum;
    }

    const int agg = (b * NCn + k) * Dn + d4;
    *reinterpret_cast<float4*>(&g_P[agg]) = make_float4(P0, P1, P2, P3);
    *reinterpret_cast<float4*>(&g_Q[agg]) = make_float4(Q0, Q1, Q2, Q3);
}

// ============================================================================
// Pass B1: group aggregates (parallel). One CTA per (batch, group).
// ============================================================================
__global__ void __launch_bounds__(128)
passB1_kernel() {
    const int b = blockIdx.x >> 5;
    const int g = blockIdx.x & (NG - 1);
    const int d = threadIdx.x;

    float Pr[GC], Qr[GC];
#pragma unroll
    for (int kk = 0; kk < GC; ++kk) {
        const int idx = (b * NCn + g * GC + kk) * Dn + d;
        Pr[kk] = g_P[idx];
        Qr[kk] = g_Q[idx];
    }
    float P = Pr[0], Q = Qr[0];
#pragma unroll
    for (int kk = 1; kk < GC; ++kk) {
        Q = fmaf(Pr[kk], Q, Qr[kk]);
        P *= Pr[kk];
    }
    g_GP[(b * NG + g) * Dn + d] = P;
    g_GQ[(b * NG + g) * Dn + d] = Q;

    if (threadIdx.x < 32) {
        const int lane = threadIdx.x;
        const int tb = b * Sn + g * TG + lane * LPL;
        float mr[LPL], sr[LPL];
#pragma unroll
        for (int i = 0; i < LPL; ++i) { mr[i] = g_m[tb + i]; sr[i] = g_s[tb + i]; }
        float M = mr[0], S = sr[0];
#pragma unroll
        for (int i = 1; i < LPL; ++i) { S = fmaf(mr[i], S, sr[i]); M *= mr[i]; }
#pragma unroll
        for (int off = 1; off < 32; off <<= 1) {
            const float Mp = __shfl_up_sync(0xffffffffu, M, off);
            const float Sp = __shfl_up_sync(0xffffffffu, S, off);
            if (lane >= off) { S = fmaf(M, Sp, S); M = M * Mp; }
        }
        float Mex = __shfl_up_sync(0xffffffffu, M, 1);
        float Sex = __shfl_up_sync(0xffffffffu, S, 1);
        if (lane == 0) { Mex = 1.f; Sex = 0.f; }
        g_laneM[(b * NG + g) * 32 + lane] = Mex;
        g_laneS[(b * NG + g) * 32 + lane] = Sex;
        if (lane == 31) {
            g_GAM[b * NG + g] = M;
            g_GAS[b * NG + g] = S;
        }
    }
}

// ============================================================================
// Pass B3: distribute prefixes down (parallel). One CTA per (batch, group).
// ============================================================================
__global__ void __launch_bounds__(128)
passB3_kernel() {
    const int b = blockIdx.x >> 5;
    const int g = blockIdx.x & (NG - 1);
    const int d = threadIdx.x;

    float b0 = 0.f;
    {
        float GPr[NG], GQr[NG];
#pragma unroll
        for (int gg = 0; gg < NG; ++gg) {
            const int idx = (b * NG + gg) * Dn + d;
            GPr[gg] = g_GP[idx];
            GQr[gg] = g_GQ[idx];
        }
#pragma unroll
        for (int gg = 0; gg < NG; ++gg) {
            if (gg < g) b0 = fmaf(GPr[gg], b0, GQr[gg]);
        }
    }

    {
        float Pr[GC], Qr[GC];
#pragma unroll
        for (int kk = 0; kk < GC; ++kk) {
            const int idx = (b * NCn + g * GC + kk) * Dn + d;
            Pr[kk] = g_P[idx];
            Qr[kk] = g_Q[idx];
        }
#pragma unroll
        for (int kk = 0; kk < GC; ++kk) {
            g_b0[(b * NCn + g * GC + kk) * Dn + d] = b0;
            b0 = fmaf(Pr[kk], b0, Qr[kk]);
        }
    }

    if (threadIdx.x < 32) {
        const int lane = threadIdx.x;
        float M = g_GAM[b * NG + lane];
        float S = g_GAS[b * NG + lane];
#pragma unroll
        for (int off = 1; off < 32; off <<= 1) {
            const float Mp = __shfl_up_sync(0xffffffffu, M, off);
            const float Sp = __shfl_up_sync(0xffffffffu, S, off);
            if (lane >= off) { S = fmaf(M, Sp, S); M = M * Mp; }
        }
        const float a0g = (g == 0) ? 0.f : __shfl_sync(0xffffffffu, S, g - 1);

        const float Mex = g_laneM[(b * NG + g) * 32 + lane];
        const float Sex = g_laneS[(b * NG + g) * 32 + lane];
        const int tb = b * Sn + g * TG + lane * LPL;
        float mr[LPL], sr[LPL];
#pragma unroll
        for (int i = 0; i < LPL; ++i) { mr[i] = g_m[tb + i]; sr[i] = g_s[tb + i]; }
        float a = fmaf(Mex, a0g, Sex);
#pragma unroll
        for (int i = 0; i < LPL; ++i) {
            a = fmaf(mr[i], a, sr[i]);
            g_rinv[tb + i] = __fdividef(1.0f, a + 1e-8f);
        }
    }
}

// ============================================================================
// Pass C: replay + LayerNorm. LN sums batched per 4-timestep half via
// reduce-scatter; rsqrt computed once per lane; mu/rstd broadcast by shfl.
// ============================================================================
__global__ void __launch_bounds__(256)
passC_kernel(const float* __restrict__ C, const float* __restrict__ V,
             const float* __restrict__ W, const float* __restrict__ enc,
             const float* __restrict__ tmod, const float* __restrict__ cmod,
             const float* __restrict__ lnw, const float* __restrict__ lnb,
             float* __restrict__ out) {
    const int warp = (blockIdx.x * blockDim.x + threadIdx.x) >> 5;
    const int lane = threadIdx.x & 31;
    const int b = warp >> 9;
    const int k = warp & (NCn - 1);
    const int t0 = k * Ln;
    const int d4 = lane * 4;

    const uint64_t pol = pol_evict_first();

    float rv = 0.f;
    if (lane < Ln) rv = g_rinv[b * Sn + t0 + lane];

    const float4 tm = *reinterpret_cast<const float4*>(tmod + d4);
    const float4 cm = *reinterpret_cast<const float4*>(cmod + d4);
    const float4 eb = *reinterpret_cast<const float4*>(enc + b * Dn + d4);
    const float ctx0 = fsig(eb.x * cm.x) * eb.x;
    const float ctx1 = fsig(eb.y * cm.y) * eb.y;
    const float ctx2 = fsig(eb.z * cm.z) * eb.z;
    const float ctx3 = fsig(eb.w * cm.w) * eb.w;
    const float4 lw = *reinterpret_cast<const float4*>(lnw + d4);
    const float4 lb = *reinterpret_cast<const float4*>(lnb + d4);

    float4 bst = *reinterpret_cast<const float4*>(&g_b0[(b * NCn + k) * Dn + d4]);

    const size_t base = ((size_t)b * Sn + t0) * Dn + d4;
    const float4* pC = reinterpret_cast<const float4*>(C + base);
    const float4* pV = reinterpret_cast<const float4*>(V + base);
    const float4* pW = reinterpret_cast<const float4*>(W + base);
    float4* pO = reinterpret_cast<float4*>(out + base);

#pragma unroll
    for (int half = 0; half < 2; ++half) {
        float4 ot[4];
        float ls[4], lq[4];
#pragma unroll
        for (int tt = 0; tt < 4; ++tt) {
            const int t = half * 4 + tt;
            const float4 c = ldg_pol(pC + t * (Dn / 4), pol);
            const float4 v = ldg_pol(pV + t * (Dn / 4), pol);
            const float4 w = ldg_pol(pW + t * (Dn / 4), pol);

            const float dd0 = fsig(w.x * tm.x), dd1 = fsig(w.y * tm.y);
            const float dd2 = fsig(w.z * tm.z), dd3 = fsig(w.w * tm.w);
            const float e0 = __expf(c.x), e1 = __expf(c.y);
            const float e2 = __expf(c.z), e3 = __expf(c.w);

            bst.x = fmaf(dd0, bst.x, fmaf(e0, v.x, ctx0));
            bst.y = fmaf(dd1, bst.y, fmaf(e1, v.y, ctx1));
            bst.z = fmaf(dd2, bst.z, fmaf(e2, v.z, ctx2));
            bst.w = fmaf(dd3, bst.w, fmaf(e3, v.w, ctx3));

            const float rinv = __shfl_sync(0xffffffffu, rv, t);
            float4 o;
            o.x = bst.x * rinv; o.y = bst.y * rinv;
            o.z = bst.z * rinv; o.w = bst.w * rinv;
            ot[tt] = o;
            ls[tt] = (o.x + o.y) + (o.z + o.w);
            lq[tt] = fmaf(o.x, o.x, fmaf(o.y, o.y, fmaf(o.z, o.z, o.w * o.w)));
        }

        // lane l gets LN sums for relative t = l&3
        const float lsum = rs4(ls[0], ls[1], ls[2], ls[3], lane);
        const float lsq  = rs4(lq[0], lq[1], lq[2], lq[3], lane);
        const float mu   = lsum * (1.0f / (float)Dn);
        const float var  = fmaf(-mu, mu, lsq * (1.0f / (float)Dn));
        const float rstd = rsqrtf(var + 1e-5f);

#pragma unroll
        for (int tt = 0; tt < 4; ++tt) {
            const int t = half * 4 + tt;
            const float mu_t   = __shfl_sync(0xffffffffu, mu, tt);
            const float rstd_t = __shfl_sync(0xffffffffu, rstd, tt);
            float4 r;
            r.x = fmaf((ot[tt].x - mu_t) * rstd_t, lw.x, lb.x);
            r.y = fmaf((ot[tt].y - mu_t) * rstd_t, lw.y, lb.y);
            r.z = fmaf((ot[tt].z - mu_t) * rstd_t, lw.z, lb.z);
            r.w = fmaf((ot[tt].w - mu_t) * rstd_t, lw.w, lb.w);
            stg_stream(pO + t * (Dn / 4), r);
        }
    }
}

// ============================================================================
extern "C" void kernel_launch(void* const* d_in, const int* in_sizes, int n_in,
                              void* d_out, int out_size) {
    (void)in_sizes; (void)n_in; (void)out_size;
    const float* C    = (const float*)d_in[0];
    const float* V    = (const float*)d_in[1];
    const float* W    = (const float*)d_in[2];
    const float* enc  = (const float*)d_in[3];
    const float* tmod = (const float*)d_in[4];
    const float* cmod = (const float*)d_in[5];
    const float* lnw  = (const float*)d_in[6];
    const float* lnb  = (const float*)d_in[7];
    float* out = (float*)d_out;

    const int warpsTotal = Bn * NCn;            // 8192
    const int blocks = warpsTotal / 8;          // 1024 blocks of 256 threads

    passA_kernel<<<blocks, 256>>>(C, V, W, enc, tmod, cmod);
    passB1_kernel<<<Bn * NG, 128>>>();
    passB3_kernel<<<Bn * NG, 128>>>();
    passC_kernel<<<blocks, 256>>>(C, V, W, enc, tmod, cmod, lnw, lnb, out);
}